// round 1
// baseline (speedup 1.0000x reference)
#include <cuda_runtime.h>

// DendriticBranchLayerSparse
//   x:           [1024, 32768] f32   (d_in[0])
//   t:           [1024]        f32   (d_in[1])
//   weight_vals: [32768]       f32   (d_in[2])
//   t_weights:   [8192, 1]     f32   (d_in[3])
//   out:         [1024, 8192]  f32
//
// out[b,o] = sum_{k<4} weight_vals[4o+k] * x[b,4o+k] + t[b]*t_weights[o]

static constexpr int BATCH    = 1024;
static constexpr int NUM_OUT  = 8192;
static constexpr int BF       = 4;
static constexpr int OQ_PER_ROW = NUM_OUT / 4;          // 2048 output-quads per batch row
static constexpr int X4_PER_ROW = (NUM_OUT * BF) / 4;   // 8192 float4 per x row

__global__ void __launch_bounds__(256)
dendritic_kernel(const float4* __restrict__ x,
                 const float*  __restrict__ t,
                 const float4* __restrict__ w,    // weight_vals as float4 (one per output)
                 const float4* __restrict__ tw4,  // t_weights as float4 (quad of outputs)
                 float4* __restrict__ out)
{
    int idx = blockIdx.x * blockDim.x + threadIdx.x;   // one thread = 4 outputs
    int b  = idx >> 11;            // / OQ_PER_ROW (2048)
    int oq = idx & (OQ_PER_ROW - 1);

    const float tb = t[b];
    const float4* xg = x + (size_t)b * X4_PER_ROW + (size_t)oq * 4;

    // x: 4 independent float4 loads (64B, MLP=4)
    float4 x0 = xg[0];
    float4 x1 = xg[1];
    float4 x2 = xg[2];
    float4 x3 = xg[3];

    float4 w0 = __ldg(&w[oq * 4 + 0]);
    float4 w1 = __ldg(&w[oq * 4 + 1]);
    float4 w2 = __ldg(&w[oq * 4 + 2]);
    float4 w3 = __ldg(&w[oq * 4 + 3]);
    float4 twv = __ldg(&tw4[oq]);

    float4 res;
    res.x = fmaf(x0.x, w0.x, fmaf(x0.y, w0.y, fmaf(x0.z, w0.z, fmaf(x0.w, w0.w, tb * twv.x))));
    res.y = fmaf(x1.x, w1.x, fmaf(x1.y, w1.y, fmaf(x1.z, w1.z, fmaf(x1.w, w1.w, tb * twv.y))));
    res.z = fmaf(x2.x, w2.x, fmaf(x2.y, w2.y, fmaf(x2.z, w2.z, fmaf(x2.w, w2.w, tb * twv.z))));
    res.w = fmaf(x3.x, w3.x, fmaf(x3.y, w3.y, fmaf(x3.z, w3.z, fmaf(x3.w, w3.w, tb * twv.w))));

    out[(size_t)b * OQ_PER_ROW + oq] = res;
}

extern "C" void kernel_launch(void* const* d_in, const int* in_sizes, int n_in,
                              void* d_out, int out_size)
{
    const float4* x   = (const float4*)d_in[0];
    const float*  t   = (const float*) d_in[1];
    const float4* w   = (const float4*)d_in[2];
    const float4* tw4 = (const float4*)d_in[3];
    float4* out = (float4*)d_out;

    const int total_threads = BATCH * OQ_PER_ROW;  // 2,097,152
    const int block = 256;
    const int grid  = total_threads / block;       // 8192

    dendritic_kernel<<<grid, block>>>(x, t, w, tw4, out);
}

// round 3
// speedup vs baseline: 1.2323x; 1.2323x over previous
#include <cuda_runtime.h>

// DendriticBranchLayerSparse
//   x:           [1024, 32768] f32   (d_in[0])   viewed as [1024, 8192] float4
//   t:           [1024]        f32   (d_in[1])
//   weight_vals: [32768]       f32   (d_in[2])   viewed as [8192] float4 (one per output)
//   t_weights:   [8192, 1]     f32   (d_in[3])
//   out:         [1024, 8192]  f32
//
// out[b,o] = dot(w4[o], x4[b,o]) + t[b]*t_weights[o]
//
// Mapping: thread <-> output column o; weights live in registers and are
// reused across R batch rows, cutting L1tex traffic ~2x vs per-(b,o) fetch.

static constexpr int BATCH   = 1024;
static constexpr int NUM_OUT = 8192;
static constexpr int R       = 16;   // batch rows per thread

__global__ void __launch_bounds__(256)
dendritic_kernel(const float4* __restrict__ x4,
                 const float*  __restrict__ t,
                 const float4* __restrict__ w4,
                 const float*  __restrict__ tw,
                 float* __restrict__ out)
{
    int idx = blockIdx.x * blockDim.x + threadIdx.x;
    int o  = idx & (NUM_OUT - 1);       // output column (lane-consecutive -> coalesced)
    int rg = idx >> 13;                 // row-group index
    int b0 = rg * R;

    // Weights: loaded ONCE, reused for R rows
    const float4 w   = __ldg(&w4[o]);
    const float  twv = __ldg(&tw[o]);

    const float4* xrow = x4 + (size_t)b0 * NUM_OUT + o;
    float*        orow = out + (size_t)b0 * NUM_OUT + o;

    #pragma unroll 4
    for (int r = 0; r < R; r++) {
        float4 xv = xrow[(size_t)r * NUM_OUT];
        float  tb = t[b0 + r];                    // warp-uniform broadcast
        float  res = fmaf(xv.x, w.x,
                     fmaf(xv.y, w.y,
                     fmaf(xv.z, w.z,
                     fmaf(xv.w, w.w, tb * twv))));
        orow[(size_t)r * NUM_OUT] = res;
    }
}

extern "C" void kernel_launch(void* const* d_in, const int* in_sizes, int n_in,
                              void* d_out, int out_size)
{
    const float4* x4 = (const float4*)d_in[0];
    const float*  t  = (const float*) d_in[1];
    const float4* w4 = (const float4*)d_in[2];
    const float*  tw = (const float*) d_in[3];
    float* out = (float*)d_out;

    const int total_threads = NUM_OUT * (BATCH / R);  // 8192 * 64 = 524288
    const int block = 256;
    const int grid  = total_threads / block;          // 2048

    dendritic_kernel<<<grid, block>>>(x4, t, w4, tw, out);
}